// round 1
// baseline (speedup 1.0000x reference)
#include <cuda_runtime.h>
#include <cstdint>

namespace {

constexpr int S_STATES = 1024;   // 2^10 states
constexpr int T_STEPS  = 64;     // (16*16)/4 chunks per block
constexpr int NTH      = 256;    // threads per CTA: thread k owns states 4k..4k+3
constexpr int NBLK     = 4096;   // 64x64 data blocks
constexpr int ROWS     = 1024;

// cost chain: cn + cb.x*x.x + ... where x is pre-scaled by -2
__device__ __forceinline__ float costf(const float4 cb, float cn, const float4 x) {
    return fmaf(cb.w, x.w, fmaf(cb.z, x.z, fmaf(cb.y, x.y, fmaf(cb.x, x.x, cn))));
}

__global__ __launch_bounds__(NTH)
void viterbi_kernel(const float* __restrict__ array,
                    const float* __restrict__ codebook,
                    float* __restrict__ out,
                    int out_size)
{
    __shared__ float alpha[2][S_STATES];          // ping-pong alpha
    __shared__ float4 xs[T_STEPS];                // -2 * x chunks
    __shared__ unsigned char bpSh[T_STEPS][NTH];  // 2-bit j per state-group per step
    __shared__ int   path[T_STEPS];
    __shared__ float redv[8];
    __shared__ int   redi[8];

    const int k  = threadIdx.x;       // 0..255 : state group
    const int b  = blockIdx.x;        // 0..4095
    const int br = b >> 6;
    const int bc = b & 63;

    // ---- load this block's 256 elements, pre-scaled by -2, into xs ----
    {
        int r = k >> 4, c = k & 15;
        float v = array[(br * 16 + r) * ROWS + (bc * 16 + c)];
        reinterpret_cast<float*>(xs)[k] = -2.0f * v;
    }

    // ---- codebook rows 4k..4k+3 into registers (fixed for all steps) ----
    const float4* cb4 = reinterpret_cast<const float4*>(codebook);
    float4 cb0 = __ldg(cb4 + 4 * k + 0);
    float4 cb1 = __ldg(cb4 + 4 * k + 1);
    float4 cb2 = __ldg(cb4 + 4 * k + 2);
    float4 cb3 = __ldg(cb4 + 4 * k + 3);
    float cn0 = fmaf(cb0.w, cb0.w, fmaf(cb0.z, cb0.z, fmaf(cb0.y, cb0.y, cb0.x * cb0.x)));
    float cn1 = fmaf(cb1.w, cb1.w, fmaf(cb1.z, cb1.z, fmaf(cb1.y, cb1.y, cb1.x * cb1.x)));
    float cn2 = fmaf(cb2.w, cb2.w, fmaf(cb2.z, cb2.z, fmaf(cb2.y, cb2.y, cb2.x * cb2.x)));
    float cn3 = fmaf(cb3.w, cb3.w, fmaf(cb3.z, cb3.z, fmaf(cb3.y, cb3.y, cb3.x * cb3.x)));

    __syncthreads();

    // ---- init: alpha0 = cost(x0), free initial state ----
    float4 x0 = xs[0];
    float v0 = costf(cb0, cn0, x0);
    float v1 = costf(cb1, cn1, x0);
    float v2 = costf(cb2, cn2, x0);
    float v3 = costf(cb3, cn3, x0);
    reinterpret_cast<float4*>(alpha[0])[k] = make_float4(v0, v1, v2, v3);
    __syncthreads();

    // ---- forward recursion: 63 steps ----
#pragma unroll 2
    for (int t = 1; t < T_STEPS; ++t) {
        const float* ap = alpha[(t + 1) & 1];
        // the 4 predecessors are shared by all 4 states this thread owns
        float a0 = ap[k];
        float a1 = ap[k + 256];
        float a2 = ap[k + 512];
        float a3 = ap[k + 768];
        float m = a0; int j = 0;                 // strict < -> first-occurrence argmin
        if (a1 < m) { m = a1; j = 1; }
        if (a2 < m) { m = a2; j = 2; }
        if (a3 < m) { m = a3; j = 3; }
        bpSh[t][k] = (unsigned char)j;

        float4 xt = xs[t];
        v0 = m + costf(cb0, cn0, xt);
        v1 = m + costf(cb1, cn1, xt);
        v2 = m + costf(cb2, cn2, xt);
        v3 = m + costf(cb3, cn3, xt);
        reinterpret_cast<float4*>(alpha[t & 1])[k] = make_float4(v0, v1, v2, v3);
        __syncthreads();
    }

    // ---- final argmin over 1024 states (first-occurrence semantics) ----
    float bm = v0; int bi = 4 * k;
    if (v1 < bm) { bm = v1; bi = 4 * k + 1; }
    if (v2 < bm) { bm = v2; bi = 4 * k + 2; }
    if (v3 < bm) { bm = v3; bi = 4 * k + 3; }
#pragma unroll
    for (int off = 16; off; off >>= 1) {
        float om = __shfl_down_sync(0xffffffffu, bm, off);
        int   oi = __shfl_down_sync(0xffffffffu, bi, off);
        if (om < bm || (om == bm && oi < bi)) { bm = om; bi = oi; }
    }
    if ((k & 31) == 0) { redv[k >> 5] = bm; redi[k >> 5] = bi; }
    __syncthreads();

    // ---- backtrack (single thread; cheap, hidden by co-resident CTAs) ----
    if (k == 0) {
        float m = redv[0]; int s = redi[0];
#pragma unroll
        for (int w = 1; w < 8; ++w) {
            if (redv[w] < m || (redv[w] == m && redi[w] < s)) { m = redv[w]; s = redi[w]; }
        }
        path[T_STEPS - 1] = s;
        for (int t = T_STEPS - 1; t >= 1; --t) {
            int kk = s >> 2;
            int j  = bpSh[t][kk];
            s = kk + (j << 8);            // prev = (s>>2) + j*HI, HI = 256
            path[t - 1] = s;
        }
    }
    __syncthreads();

    // ---- emit: rec (exact codebook gather) + states ----
    if (k < T_STEPS) {
        int t = k;
        int s = path[t];
        float4 val = __ldg(cb4 + s);
        int row = br * 16 + (t >> 2);
        int col = bc * 16 + ((t & 3) << 2);
        reinterpret_cast<float4*>(out + row * ROWS + col)[0] = val;
        int sidx = ROWS * ROWS + b * T_STEPS + t;
        if (sidx < out_size) out[sidx] = (float)s;   // states as float values (concat-promoted)
    }
}

} // namespace

extern "C" void kernel_launch(void* const* d_in, const int* in_sizes, int n_in,
                              void* d_out, int out_size) {
    const float* array    = (const float*)d_in[0];
    const float* codebook = (const float*)d_in[1];
    (void)in_sizes; (void)n_in;
    float* out = (float*)d_out;
    viterbi_kernel<<<NBLK, NTH>>>(array, codebook, out, out_size);
}